// round 1
// baseline (speedup 1.0000x reference)
#include <cuda_runtime.h>
#include <cuda_bf16.h>

// Problem constants
#define BATCH   4
#define NSEQ    2048
#define DIM     512
#define HEADS   8
#define DHEAD   64
#define INNER   512          // HEADS*DHEAD
#define QKVN    1536         // 3*INNER
#define SCALE   0.125f       // 64^-0.5
#define THRESH  0.01f

// Scratch (device globals: allocation-free per harness rules)
__device__ float g_qkv[(size_t)BATCH * NSEQ * QKVN];                 // 50.3 MB
__device__ float g_scores[(size_t)BATCH * HEADS * NSEQ * NSEQ];      // 537 MB
__device__ float g_ctx[(size_t)BATCH * NSEQ * INNER];                // 16.8 MB

// ---------------------------------------------------------------------------
// Generic SGEMM: C[M,N] = A[M,K] @ B[K,N] + bias[N]
// 128x128 tile, BK=8, 256 threads, 8x8 per thread. M,N multiples of 128, K of 8.
// ---------------------------------------------------------------------------
__global__ __launch_bounds__(256) void sgemm_bias_kernel(
    const float* __restrict__ A, const float* __restrict__ Bm,
    const float* __restrict__ bias, float* __restrict__ C,
    int M, int Nn, int K)
{
    __shared__ float As[8][128];
    __shared__ float Bs[8][128];
    const int tid = threadIdx.x;
    const int bx = blockIdx.x, by = blockIdx.y;
    const int tx = tid & 15, ty = tid >> 4;
    const int la_r = tid >> 1, la_c = (tid & 1) * 4;   // A: 128 rows x 8 cols
    const int lb_r = tid >> 5, lb_c = (tid & 31) * 4;  // B: 8 rows x 128 cols

    const float* Ap = A + (size_t)(by * 128 + la_r) * K + la_c;
    const float* Bp = Bm + (size_t)lb_r * Nn + bx * 128 + lb_c;

    float acc[8][8] = {};
    for (int k0 = 0; k0 < K; k0 += 8) {
        float4 a4 = *(const float4*)(Ap + k0);
        float4 b4 = *(const float4*)(Bp + (size_t)k0 * Nn);
        As[la_c + 0][la_r] = a4.x; As[la_c + 1][la_r] = a4.y;
        As[la_c + 2][la_r] = a4.z; As[la_c + 3][la_r] = a4.w;
        *(float4*)&Bs[lb_r][lb_c] = b4;
        __syncthreads();
        #pragma unroll
        for (int kk = 0; kk < 8; kk++) {
            float ar[8], br[8];
            #pragma unroll
            for (int i = 0; i < 8; i++) ar[i] = As[kk][ty * 8 + i];
            #pragma unroll
            for (int j = 0; j < 8; j++) br[j] = Bs[kk][tx * 8 + j];
            #pragma unroll
            for (int i = 0; i < 8; i++)
                #pragma unroll
                for (int j = 0; j < 8; j++)
                    acc[i][j] = fmaf(ar[i], br[j], acc[i][j]);
        }
        __syncthreads();
    }

    float bv[8];
    #pragma unroll
    for (int j = 0; j < 8; j++) bv[j] = bias ? bias[bx * 128 + tx * 8 + j] : 0.0f;
    #pragma unroll
    for (int i = 0; i < 8; i++) {
        size_t roff = (size_t)(by * 128 + ty * 8 + i) * Nn + bx * 128 + tx * 8;
        float4 o0 = make_float4(acc[i][0] + bv[0], acc[i][1] + bv[1],
                                acc[i][2] + bv[2], acc[i][3] + bv[3]);
        float4 o1 = make_float4(acc[i][4] + bv[4], acc[i][5] + bv[5],
                                acc[i][6] + bv[6], acc[i][7] + bv[7]);
        *(float4*)(C + roff)     = o0;
        *(float4*)(C + roff + 4) = o1;
    }
}

// ---------------------------------------------------------------------------
// Scores: S[bh,i,j] = SCALE * sum_d q[b,i,h,d] * k[b,j,h,d]   (NT gemm, K=64)
// 128x128 tile, 256 threads, 8x8 per thread.
// ---------------------------------------------------------------------------
__global__ __launch_bounds__(256) void scores_kernel(float* __restrict__ S)
{
    __shared__ float Qs[8][128];
    __shared__ float Ks[8][128];
    const int tid = threadIdx.x;
    const int bx = blockIdx.x;   // j tile
    const int by = blockIdx.y;   // i tile
    const int bh = blockIdx.z;   // 0..31
    const int b = bh >> 3, h = bh & 7;
    const int tx = tid & 15, ty = tid >> 4;
    const int lr = tid >> 1, lc = (tid & 1) * 4;

    const float* qbase = g_qkv + (size_t)b * NSEQ * QKVN + h * DHEAD;
    const float* qp = qbase + (size_t)(by * 128 + lr) * QKVN + lc;
    const float* kp = qbase + INNER + (size_t)(bx * 128 + lr) * QKVN + lc;

    float acc[8][8] = {};
    for (int d0 = 0; d0 < DHEAD; d0 += 8) {
        float4 q4 = *(const float4*)(qp + d0);
        float4 k4 = *(const float4*)(kp + d0);
        Qs[lc + 0][lr] = q4.x; Qs[lc + 1][lr] = q4.y;
        Qs[lc + 2][lr] = q4.z; Qs[lc + 3][lr] = q4.w;
        Ks[lc + 0][lr] = k4.x; Ks[lc + 1][lr] = k4.y;
        Ks[lc + 2][lr] = k4.z; Ks[lc + 3][lr] = k4.w;
        __syncthreads();
        #pragma unroll
        for (int kk = 0; kk < 8; kk++) {
            float ar[8], br[8];
            #pragma unroll
            for (int i = 0; i < 8; i++) ar[i] = Qs[kk][ty * 8 + i];
            #pragma unroll
            for (int j = 0; j < 8; j++) br[j] = Ks[kk][tx * 8 + j];
            #pragma unroll
            for (int i = 0; i < 8; i++)
                #pragma unroll
                for (int j = 0; j < 8; j++)
                    acc[i][j] = fmaf(ar[i], br[j], acc[i][j]);
        }
        __syncthreads();
    }

    float* Sp = S + ((size_t)bh * NSEQ + by * 128 + ty * 8) * NSEQ + bx * 128 + tx * 8;
    #pragma unroll
    for (int i = 0; i < 8; i++) {
        float4 o0 = make_float4(acc[i][0] * SCALE, acc[i][1] * SCALE,
                                acc[i][2] * SCALE, acc[i][3] * SCALE);
        float4 o1 = make_float4(acc[i][4] * SCALE, acc[i][5] * SCALE,
                                acc[i][6] * SCALE, acc[i][7] * SCALE);
        *(float4*)(Sp + (size_t)i * NSEQ)     = o0;
        *(float4*)(Sp + (size_t)i * NSEQ + 4) = o1;
    }
}

// ---------------------------------------------------------------------------
// Row softmax + threshold, in place. One block (256 threads) per row of 2048.
// ---------------------------------------------------------------------------
__global__ __launch_bounds__(256) void softmax_kernel(float* __restrict__ S)
{
    const size_t row = blockIdx.x;
    float* p = S + row * NSEQ;
    const int t = threadIdx.x;
    __shared__ float red[256];

    float v[8];
    #pragma unroll
    for (int i = 0; i < 8; i++) v[i] = p[t + 256 * i];

    float m = v[0];
    #pragma unroll
    for (int i = 1; i < 8; i++) m = fmaxf(m, v[i]);
    red[t] = m; __syncthreads();
    for (int s = 128; s > 0; s >>= 1) {
        if (t < s) red[t] = fmaxf(red[t], red[t + s]);
        __syncthreads();
    }
    m = red[0];
    __syncthreads();

    float sum = 0.0f;
    #pragma unroll
    for (int i = 0; i < 8; i++) { v[i] = __expf(v[i] - m); sum += v[i]; }
    red[t] = sum; __syncthreads();
    for (int s = 128; s > 0; s >>= 1) {
        if (t < s) red[t] += red[t + s];
        __syncthreads();
    }
    float inv = 1.0f / red[0];

    #pragma unroll
    for (int i = 0; i < 8; i++) {
        float pv = v[i] * inv;
        p[t + 256 * i] = (pv > THRESH) ? pv : 0.0f;
    }
}

// ---------------------------------------------------------------------------
// PV: ctx[b,i,h*64+d] = sum_j P[bh,i,j] * v[b,j,h,d]
// 128x64 tile, BK=16, 256 threads (16x16), 8x4 per thread.
// ---------------------------------------------------------------------------
__global__ __launch_bounds__(256) void av_kernel(const float* __restrict__ S)
{
    __shared__ float Ps[16][128];
    __shared__ float Vs[16][64];
    const int tid = threadIdx.x;
    const int by = blockIdx.x;   // i tile (0..15)
    const int bh = blockIdx.y;   // 0..31
    const int b = bh >> 3, h = bh & 7;
    const int tx = tid & 15, ty = tid >> 4;
    const int lpr = tid >> 2, lpc = (tid & 3) * 4;   // P: rows lpr and lpr+64
    const int lvr = tid >> 4, lvc = (tid & 15) * 4;  // V: 16 rows x 64 cols

    const float* Sp = S + ((size_t)bh * NSEQ + by * 128 + lpr) * NSEQ + lpc;
    const float* vp = g_qkv + (size_t)b * NSEQ * QKVN + 2 * INNER + h * DHEAD
                    + (size_t)lvr * QKVN + lvc;

    float acc[8][4] = {};
    for (int k0 = 0; k0 < NSEQ; k0 += 16) {
        float4 p0 = *(const float4*)(Sp + k0);
        float4 p1 = *(const float4*)(Sp + (size_t)64 * NSEQ + k0);
        float4 v4 = *(const float4*)(vp + (size_t)k0 * QKVN);
        Ps[lpc + 0][lpr] = p0.x; Ps[lpc + 1][lpr] = p0.y;
        Ps[lpc + 2][lpr] = p0.z; Ps[lpc + 3][lpr] = p0.w;
        Ps[lpc + 0][lpr + 64] = p1.x; Ps[lpc + 1][lpr + 64] = p1.y;
        Ps[lpc + 2][lpr + 64] = p1.z; Ps[lpc + 3][lpr + 64] = p1.w;
        *(float4*)&Vs[lvr][lvc] = v4;
        __syncthreads();
        #pragma unroll
        for (int kk = 0; kk < 16; kk++) {
            float ar[8], br[4];
            #pragma unroll
            for (int i = 0; i < 8; i++) ar[i] = Ps[kk][ty * 8 + i];
            #pragma unroll
            for (int j = 0; j < 4; j++) br[j] = Vs[kk][tx * 4 + j];
            #pragma unroll
            for (int i = 0; i < 8; i++)
                #pragma unroll
                for (int j = 0; j < 4; j++)
                    acc[i][j] = fmaf(ar[i], br[j], acc[i][j]);
        }
        __syncthreads();
    }

    #pragma unroll
    for (int i = 0; i < 8; i++) {
        size_t off = ((size_t)b * NSEQ + by * 128 + ty * 8 + i) * INNER
                   + h * DHEAD + tx * 4;
        *(float4*)(g_ctx + off) = make_float4(acc[i][0], acc[i][1], acc[i][2], acc[i][3]);
    }
}

// ---------------------------------------------------------------------------
extern "C" void kernel_launch(void* const* d_in, const int* in_sizes, int n_in,
                              void* d_out, int out_size)
{
    const float* x    = (const float*)d_in[0];
    const float* Wqkv = (const float*)d_in[1];
    const float* bqkv = (const float*)d_in[2];
    const float* Wout = (const float*)d_in[3];
    const float* bout = (const float*)d_in[4];
    float* out = (float*)d_out;

    float *qkv_ptr, *sc_ptr, *ctx_ptr;
    cudaGetSymbolAddress((void**)&qkv_ptr, g_qkv);
    cudaGetSymbolAddress((void**)&sc_ptr,  g_scores);
    cudaGetSymbolAddress((void**)&ctx_ptr, g_ctx);

    // 1) QKV projection: [8192,512] @ [512,1536] + bqkv
    sgemm_bias_kernel<<<dim3(QKVN / 128, (BATCH * NSEQ) / 128), 256>>>(
        x, Wqkv, bqkv, qkv_ptr, BATCH * NSEQ, QKVN, DIM);

    // 2) Attention scores
    scores_kernel<<<dim3(NSEQ / 128, NSEQ / 128, BATCH * HEADS), 256>>>(sc_ptr);

    // 3) Softmax + threshold (one block per row)
    softmax_kernel<<<BATCH * HEADS * NSEQ, 256>>>(sc_ptr);

    // 4) attn @ V -> ctx
    av_kernel<<<dim3(NSEQ / 128, BATCH * HEADS), 256>>>(sc_ptr);

    // 5) Output projection: [8192,512] @ [512,512] + bout
    sgemm_bias_kernel<<<dim3(INNER / 128, (BATCH * NSEQ) / 128), 256>>>(
        ctx_ptr, Wout, bout, out, BATCH * NSEQ, INNER, INNER);
}

// round 4
// speedup vs baseline: 1.0463x; 1.0463x over previous
#include <cuda_runtime.h>
#include <cstdint>

// Problem constants
#define BATCH   4
#define NSEQ    2048
#define DIM     512
#define HEADS   8
#define DHEAD   64
#define INNER   512          // HEADS*DHEAD
#define QKVN    1536         // 3*INNER
#define SCALE   0.125f       // 64^-0.5
#define THRESH  0.01f

// Scratch (device globals: allocation-free per harness rules)
__device__ float  g_qkv[(size_t)BATCH * NSEQ * QKVN];                // 50.3 MB
__device__ float  g_scores[(size_t)BATCH * HEADS * NSEQ * NSEQ];     // 537 MB
__device__ float  g_ctx[(size_t)BATCH * NSEQ * INNER];               // 16.8 MB
__device__ float2 g_stats[(size_t)BATCH * HEADS * NSEQ];             // (max, sum) per row

// ---------------------------------------------------------------------------
// fp32 SGEMM (decision-critical path): C[M,N] = A[M,K] @ B[K,N] + bias[N]
// (verbatim from R1 — validated)
// ---------------------------------------------------------------------------
__global__ __launch_bounds__(256) void sgemm_bias_kernel(
    const float* __restrict__ A, const float* __restrict__ Bm,
    const float* __restrict__ bias, float* __restrict__ C,
    int M, int Nn, int K)
{
    __shared__ float As[8][128];
    __shared__ float Bs[8][128];
    const int tid = threadIdx.x;
    const int bx = blockIdx.x, by = blockIdx.y;
    const int tx = tid & 15, ty = tid >> 4;
    const int la_r = tid >> 1, la_c = (tid & 1) * 4;
    const int lb_r = tid >> 5, lb_c = (tid & 31) * 4;

    const float* Ap = A + (size_t)(by * 128 + la_r) * K + la_c;
    const float* Bp = Bm + (size_t)lb_r * Nn + bx * 128 + lb_c;

    float acc[8][8] = {};
    for (int k0 = 0; k0 < K; k0 += 8) {
        float4 a4 = *(const float4*)(Ap + k0);
        float4 b4 = *(const float4*)(Bp + (size_t)k0 * Nn);
        As[la_c + 0][la_r] = a4.x; As[la_c + 1][la_r] = a4.y;
        As[la_c + 2][la_r] = a4.z; As[la_c + 3][la_r] = a4.w;
        *(float4*)&Bs[lb_r][lb_c] = b4;
        __syncthreads();
        #pragma unroll
        for (int kk = 0; kk < 8; kk++) {
            float ar[8], br[8];
            #pragma unroll
            for (int i = 0; i < 8; i++) ar[i] = As[kk][ty * 8 + i];
            #pragma unroll
            for (int j = 0; j < 8; j++) br[j] = Bs[kk][tx * 8 + j];
            #pragma unroll
            for (int i = 0; i < 8; i++)
                #pragma unroll
                for (int j = 0; j < 8; j++)
                    acc[i][j] = fmaf(ar[i], br[j], acc[i][j]);
        }
        __syncthreads();
    }

    float bv[8];
    #pragma unroll
    for (int j = 0; j < 8; j++) bv[j] = bias ? bias[bx * 128 + tx * 8 + j] : 0.0f;
    #pragma unroll
    for (int i = 0; i < 8; i++) {
        size_t roff = (size_t)(by * 128 + ty * 8 + i) * Nn + bx * 128 + tx * 8;
        float4 o0 = make_float4(acc[i][0] + bv[0], acc[i][1] + bv[1],
                                acc[i][2] + bv[2], acc[i][3] + bv[3]);
        float4 o1 = make_float4(acc[i][4] + bv[4], acc[i][5] + bv[5],
                                acc[i][6] + bv[6], acc[i][7] + bv[7]);
        *(float4*)(C + roff)     = o0;
        *(float4*)(C + roff + 4) = o1;
    }
}

// ---------------------------------------------------------------------------
// fp32 scores (decision-critical): S = SCALE * q . k^T  (verbatim from R1)
// ---------------------------------------------------------------------------
__global__ __launch_bounds__(256) void scores_kernel(float* __restrict__ S)
{
    __shared__ float Qs[8][128];
    __shared__ float Ks[8][128];
    const int tid = threadIdx.x;
    const int bx = blockIdx.x;
    const int by = blockIdx.y;
    const int bh = blockIdx.z;
    const int b = bh >> 3, h = bh & 7;
    const int tx = tid & 15, ty = tid >> 4;
    const int lr = tid >> 1, lc = (tid & 1) * 4;

    const float* qbase = g_qkv + (size_t)b * NSEQ * QKVN + h * DHEAD;
    const float* qp = qbase + (size_t)(by * 128 + lr) * QKVN + lc;
    const float* kp = qbase + INNER + (size_t)(bx * 128 + lr) * QKVN + lc;

    float acc[8][8] = {};
    for (int d0 = 0; d0 < DHEAD; d0 += 8) {
        float4 q4 = *(const float4*)(qp + d0);
        float4 k4 = *(const float4*)(kp + d0);
        Qs[lc + 0][lr] = q4.x; Qs[lc + 1][lr] = q4.y;
        Qs[lc + 2][lr] = q4.z; Qs[lc + 3][lr] = q4.w;
        Ks[lc + 0][lr] = k4.x; Ks[lc + 1][lr] = k4.y;
        Ks[lc + 2][lr] = k4.z; Ks[lc + 3][lr] = k4.w;
        __syncthreads();
        #pragma unroll
        for (int kk = 0; kk < 8; kk++) {
            float ar[8], br[8];
            #pragma unroll
            for (int i = 0; i < 8; i++) ar[i] = Qs[kk][ty * 8 + i];
            #pragma unroll
            for (int j = 0; j < 8; j++) br[j] = Ks[kk][tx * 8 + j];
            #pragma unroll
            for (int i = 0; i < 8; i++)
                #pragma unroll
                for (int j = 0; j < 8; j++)
                    acc[i][j] = fmaf(ar[i], br[j], acc[i][j]);
        }
        __syncthreads();
    }

    float* Sp = S + ((size_t)bh * NSEQ + by * 128 + ty * 8) * NSEQ + bx * 128 + tx * 8;
    #pragma unroll
    for (int i = 0; i < 8; i++) {
        float4 o0 = make_float4(acc[i][0] * SCALE, acc[i][1] * SCALE,
                                acc[i][2] * SCALE, acc[i][3] * SCALE);
        float4 o1 = make_float4(acc[i][4] * SCALE, acc[i][5] * SCALE,
                                acc[i][6] * SCALE, acc[i][7] * SCALE);
        *(float4*)(Sp + (size_t)i * NSEQ)     = o0;
        *(float4*)(Sp + (size_t)i * NSEQ + 4) = o1;
    }
}

// ---------------------------------------------------------------------------
// Row stats: per row compute (max, sum of exp(z-max)). Read-only over S.
// Numerics identical to R1's softmax reduction (same order, same __expf).
// ---------------------------------------------------------------------------
__global__ __launch_bounds__(256) void rowstats_kernel(const float* __restrict__ S)
{
    const size_t row = blockIdx.x;
    const float* p = S + row * NSEQ;
    const int t = threadIdx.x;
    __shared__ float red[256];

    float v[8];
    #pragma unroll
    for (int i = 0; i < 8; i++) v[i] = p[t + 256 * i];

    float m = v[0];
    #pragma unroll
    for (int i = 1; i < 8; i++) m = fmaxf(m, v[i]);
    red[t] = m; __syncthreads();
    for (int s = 128; s > 0; s >>= 1) {
        if (t < s) red[t] = fmaxf(red[t], red[t + s]);
        __syncthreads();
    }
    m = red[0];
    __syncthreads();

    float sum = 0.0f;
    #pragma unroll
    for (int i = 0; i < 8; i++) sum += __expf(v[i] - m);
    red[t] = sum; __syncthreads();
    for (int s = 128; s > 0; s >>= 1) {
        if (t < s) red[t] += red[t + s];
        __syncthreads();
    }
    if (t == 0) g_stats[row] = make_float2(m, red[0]);
}

// ---------------------------------------------------------------------------
// 3xTF32 helpers (smooth path)
// ---------------------------------------------------------------------------
__device__ __forceinline__ void split_tf32(float x, uint32_t& hi, uint32_t& lo) {
    uint32_t h;
    asm("cvt.rna.tf32.f32 %0, %1;" : "=r"(h) : "f"(x));
    float hf = __uint_as_float(h);
    asm("cvt.rna.tf32.f32 %0, %1;" : "=r"(lo) : "f"(x - hf));
    hi = h;
}
__device__ __forceinline__ void mma8(float* c, const uint32_t* a, const uint32_t* b) {
    asm volatile(
        "mma.sync.aligned.m16n8k8.row.col.f32.tf32.tf32.f32 "
        "{%0,%1,%2,%3},{%4,%5,%6,%7},{%8,%9},{%0,%1,%2,%3};"
        : "+f"(c[0]), "+f"(c[1]), "+f"(c[2]), "+f"(c[3])
        : "r"(a[0]), "r"(a[1]), "r"(a[2]), "r"(a[3]), "r"(b[0]), "r"(b[1]));
}
__device__ __forceinline__ void mma3(float* c, const uint32_t* ah, const uint32_t* al,
                                     const uint32_t* bh, const uint32_t* bl) {
    mma8(c, ah, bh);
    mma8(c, ah, bl);
    mma8(c, al, bh);
}

// ---------------------------------------------------------------------------
// PV (3xTF32) with inline softmax apply:
// p = exp(z - m) / sum;  p = p > THRESH ? p : 0;  ctx = P @ V
// 128x64 tile, BK=16, 8 warps (4x2), warp tile 32x32.
// ---------------------------------------------------------------------------
__global__ __launch_bounds__(256) void av_mma(const float* __restrict__ S)
{
    __shared__ uint32_t Ps[2][16][136];
    __shared__ uint32_t Vs[2][16][72];
    const int tid = threadIdx.x;
    const int bx = blockIdx.x;   // i tile (0..15)
    const int by = blockIdx.y;   // bh
    const int b = by >> 3, h = by & 7;
    const int lane = tid & 31, wid = tid >> 5;
    const int gid = lane >> 2, tig = lane & 3;
    const int wm = wid & 3, wn = wid >> 2;
    const int pr = tid >> 1, pq = (tid & 1) * 8;    // P: row pr, k off pq
    const int vr = tid >> 4, vc = (tid & 15) * 4;   // V: row vr, cols vc..vc+3

    const size_t rowg = (size_t)by * NSEQ + bx * 128 + pr;
    const float2 st = g_stats[rowg];
    const float  rm = st.x;
    const float  inv = 1.0f / st.y;

    const float* Pp = S + rowg * NSEQ + pq;
    const float* Vp = g_qkv + (size_t)b * NSEQ * QKVN + 2 * INNER + h * DHEAD
                    + (size_t)vr * QKVN + vc;

    float4 p40 = *(const float4*)Pp;
    float4 p41 = *(const float4*)(Pp + 4);
    float4 v4  = *(const float4*)Vp;

    float acc[2][4][4] = {};

    for (int k0 = 0; k0 < NSEQ; k0 += 16) {
        const float* p0 = &p40.x; const float* p1 = &p41.x;
        #pragma unroll
        for (int e = 0; e < 4; e++) {
            uint32_t h_, l_;
            float a0 = __expf(p0[e] - rm) * inv;
            a0 = (a0 > THRESH) ? a0 : 0.0f;
            split_tf32(a0, h_, l_);
            Ps[0][pq + e][pr] = h_; Ps[1][pq + e][pr] = l_;
            float a1 = __expf(p1[e] - rm) * inv;
            a1 = (a1 > THRESH) ? a1 : 0.0f;
            split_tf32(a1, h_, l_);
            Ps[0][pq + 4 + e][pr] = h_; Ps[1][pq + 4 + e][pr] = l_;
        }
        const float* vv = &v4.x;
        #pragma unroll
        for (int e = 0; e < 4; e++) {
            uint32_t h_, l_;
            split_tf32(vv[e], h_, l_);
            Vs[0][vr][vc + e] = h_; Vs[1][vr][vc + e] = l_;
        }
        __syncthreads();

        if (k0 + 16 < NSEQ) {
            p40 = *(const float4*)(Pp + k0 + 16);
            p41 = *(const float4*)(Pp + k0 + 16 + 4);
            v4  = *(const float4*)(Vp + (size_t)(k0 + 16) * QKVN);
        }

        #pragma unroll
        for (int ks = 0; ks < 16; ks += 8) {
            uint32_t afh[2][4], afl[2][4], bfh[4][2], bfl[4][2];
            #pragma unroll
            for (int i = 0; i < 2; i++) {
                int m0 = wm * 32 + i * 16;
                afh[i][0] = Ps[0][ks + tig][m0 + gid];
                afh[i][1] = Ps[0][ks + tig][m0 + gid + 8];
                afh[i][2] = Ps[0][ks + tig + 4][m0 + gid];
                afh[i][3] = Ps[0][ks + tig + 4][m0 + gid + 8];
                afl[i][0] = Ps[1][ks + tig][m0 + gid];
                afl[i][1] = Ps[1][ks + tig][m0 + gid + 8];
                afl[i][2] = Ps[1][ks + tig + 4][m0 + gid];
                afl[i][3] = Ps[1][ks + tig + 4][m0 + gid + 8];
            }
            #pragma unroll
            for (int j = 0; j < 4; j++) {
                int n0 = wn * 32 + j * 8;
                bfh[j][0] = Vs[0][ks + tig][n0 + gid];
                bfh[j][1] = Vs[0][ks + tig + 4][n0 + gid];
                bfl[j][0] = Vs[1][ks + tig][n0 + gid];
                bfl[j][1] = Vs[1][ks + tig + 4][n0 + gid];
            }
            #pragma unroll
            for (int i = 0; i < 2; i++)
                #pragma unroll
                for (int j = 0; j < 4; j++)
                    mma3(acc[i][j], afh[i], afl[i], bfh[j], bfl[j]);
        }
        __syncthreads();
    }

    #pragma unroll
    for (int i = 0; i < 2; i++) {
        int row = b * NSEQ + bx * 128 + wm * 32 + i * 16 + gid;
        #pragma unroll
        for (int j = 0; j < 4; j++) {
            int col = h * DHEAD + wn * 32 + j * 8 + tig * 2;
            *(float2*)(g_ctx + (size_t)row * INNER + col) =
                make_float2(acc[i][j][0], acc[i][j][1]);
            *(float2*)(g_ctx + (size_t)(row + 8) * INNER + col) =
                make_float2(acc[i][j][2], acc[i][j][3]);
        }
    }
}

// ---------------------------------------------------------------------------
// Out-proj (3xTF32): C[M,N] = A[M,K] @ B[K,N] + bias  (verbatim from R3)
// ---------------------------------------------------------------------------
__global__ __launch_bounds__(256) void sgemm_mma_bias(
    const float* __restrict__ A, const float* __restrict__ Bm,
    const float* __restrict__ bias, float* __restrict__ C,
    int M, int N, int K)
{
    __shared__ uint32_t As[2][16][136];
    __shared__ uint32_t Bs[2][16][136];
    const int tid = threadIdx.x;
    const int bx = blockIdx.x, by = blockIdx.y;
    const int lane = tid & 31, wid = tid >> 5;
    const int gid = lane >> 2, tig = lane & 3;
    const int wm = wid & 1, wn = wid >> 1;
    const int ar = tid >> 2, aq = tid & 3;
    const int bkr = tid >> 4, bc = (tid & 15) * 8;

    const float* Ap0 = A + (size_t)(by * 128 + ar) * K + aq * 4;
    const float* Ap1 = Ap0 + (size_t)64 * K;
    const float* Bp  = Bm + (size_t)bkr * N + bx * 128 + bc;

    float4 av0 = *(const float4*)Ap0;
    float4 av1 = *(const float4*)Ap1;
    float4 bv0 = *(const float4*)Bp;
    float4 bv1 = *(const float4*)(Bp + 4);

    float acc[4][4][4] = {};

    for (int k0 = 0; k0 < K; k0 += 16) {
        const float* a0 = &av0.x; const float* a1 = &av1.x;
        #pragma unroll
        for (int e = 0; e < 4; e++) {
            uint32_t h, l;
            split_tf32(a0[e], h, l);
            As[0][aq * 4 + e][ar] = h; As[1][aq * 4 + e][ar] = l;
            split_tf32(a1[e], h, l);
            As[0][aq * 4 + e][ar + 64] = h; As[1][aq * 4 + e][ar + 64] = l;
        }
        const float* b0p = &bv0.x; const float* b1p = &bv1.x;
        #pragma unroll
        for (int e = 0; e < 4; e++) {
            uint32_t h, l;
            split_tf32(b0p[e], h, l);
            Bs[0][bkr][bc + e] = h; Bs[1][bkr][bc + e] = l;
            split_tf32(b1p[e], h, l);
            Bs[0][bkr][bc + 4 + e] = h; Bs[1][bkr][bc + 4 + e] = l;
        }
        __syncthreads();

        if (k0 + 16 < K) {
            av0 = *(const float4*)(Ap0 + k0 + 16);
            av1 = *(const float4*)(Ap1 + k0 + 16);
            bv0 = *(const float4*)(Bp + (size_t)(k0 + 16) * N);
            bv1 = *(const float4*)(Bp + (size_t)(k0 + 16) * N + 4);
        }

        #pragma unroll
        for (int ks = 0; ks < 16; ks += 8) {
            uint32_t afh[4][4], afl[4][4], bfh[4][2], bfl[4][2];
            #pragma unroll
            for (int i = 0; i < 4; i++) {
                int m0 = wm * 64 + i * 16;
                afh[i][0] = As[0][ks + tig][m0 + gid];
                afh[i][1] = As[0][ks + tig][m0 + gid + 8];
                afh[i][2] = As[0][ks + tig + 4][m0 + gid];
                afh[i][3] = As[0][ks + tig + 4][m0 + gid + 8];
                afl[i][0] = As[1][ks + tig][m0 + gid];
                afl[i][1] = As[1][ks + tig][m0 + gid + 8];
                afl[i][2] = As[1][ks + tig + 4][m0 + gid];
                afl[i][3] = As[1][ks + tig + 4][m0 + gid + 8];
            }
            #pragma unroll
            for (int j = 0; j < 4; j++) {
                int n0 = wn * 32 + j * 8;
                bfh[j][0] = Bs[0][ks + tig][n0 + gid];
                bfh[j][1] = Bs[0][ks + tig + 4][n0 + gid];
                bfl[j][0] = Bs[1][ks + tig][n0 + gid];
                bfl[j][1] = Bs[1][ks + tig + 4][n0 + gid];
            }
            #pragma unroll
            for (int i = 0; i < 4; i++)
                #pragma unroll
                for (int j = 0; j < 4; j++)
                    mma3(acc[i][j], afh[i], afl[i], bfh[j], bfl[j]);
        }
        __syncthreads();
    }

    #pragma unroll
    for (int i = 0; i < 4; i++) {
        int row = by * 128 + wm * 64 + i * 16 + gid;
        #pragma unroll
        for (int j = 0; j < 4; j++) {
            int col = bx * 128 + wn * 32 + j * 8 + tig * 2;
            float b0 = bias ? bias[col] : 0.f;
            float b1 = bias ? bias[col + 1] : 0.f;
            *(float2*)(C + (size_t)row * N + col) =
                make_float2(acc[i][j][0] + b0, acc[i][j][1] + b1);
            *(float2*)(C + (size_t)(row + 8) * N + col) =
                make_float2(acc[i][j][2] + b0, acc[i][j][3] + b1);
        }
    }
}

// ---------------------------------------------------------------------------
extern "C" void kernel_launch(void* const* d_in, const int* in_sizes, int n_in,
                              void* d_out, int out_size)
{
    const float* x    = (const float*)d_in[0];
    const float* Wqkv = (const float*)d_in[1];
    const float* bqkv = (const float*)d_in[2];
    const float* Wout = (const float*)d_in[3];
    const float* bout = (const float*)d_in[4];
    float* out = (float*)d_out;

    float *qkv_ptr, *sc_ptr, *ctx_ptr;
    cudaGetSymbolAddress((void**)&qkv_ptr, g_qkv);
    cudaGetSymbolAddress((void**)&sc_ptr,  g_scores);
    cudaGetSymbolAddress((void**)&ctx_ptr, g_ctx);

    // 1) QKV projection (fp32, decision-critical)
    sgemm_bias_kernel<<<dim3(QKVN / 128, (BATCH * NSEQ) / 128), 256>>>(
        x, Wqkv, bqkv, qkv_ptr, BATCH * NSEQ, QKVN, DIM);

    // 2) Attention scores (fp32, decision-critical)
    scores_kernel<<<dim3(NSEQ / 128, NSEQ / 128, BATCH * HEADS), 256>>>(sc_ptr);

    // 3) Row stats (max, sumexp) — read-only pass
    rowstats_kernel<<<BATCH * HEADS * NSEQ, 256>>>(sc_ptr);

    // 4) softmax-apply + threshold + P@V (3xTF32 tensor path)
    av_mma<<<dim3(NSEQ / 128, BATCH * HEADS), 256>>>(sc_ptr);

    // 5) Output projection (3xTF32 tensor path)
    sgemm_mma_bias<<<dim3(INNER / 128, (BATCH * NSEQ) / 128), 256>>>(
        ctx_ptr, Wout, bout, out, BATCH * NSEQ, INNER, INNER);
}

// round 5
// speedup vs baseline: 1.4270x; 1.3639x over previous
#include <cuda_runtime.h>
#include <cstdint>

// Problem constants
#define BATCH   4
#define NSEQ    2048
#define DIM     512
#define HEADS   8
#define DHEAD   64
#define INNER   512          // HEADS*DHEAD
#define QKVN    1536         // 3*INNER
#define SCALE   0.125f       // 64^-0.5
#define THRESH  0.01f
#define NROWS   ((size_t)BATCH * HEADS * NSEQ)   // 65536 attention rows
#define MAXS    32                                // survivor slots per row

// Scratch (device globals: allocation-free per harness rules)
__device__ float  g_qkv[(size_t)BATCH * NSEQ * QKVN];                // 50.3 MB
__device__ float  g_scores[(size_t)BATCH * HEADS * NSEQ * NSEQ];     // 537 MB
__device__ float  g_ctx[(size_t)BATCH * NSEQ * INNER];               // 16.8 MB
__device__ float2 g_part[NROWS * 16];                                // per (row, jtile) (max, sumexp)
__device__ int    g_cnt[NROWS];
__device__ int    g_cols[NROWS * MAXS];
__device__ float  g_vals[NROWS * MAXS];

// ---------------------------------------------------------------------------
// fp32 SGEMM (decision-critical path): C[M,N] = A[M,K] @ B[K,N] + bias[N]
// (verbatim from R1 — validated)
// ---------------------------------------------------------------------------
__global__ __launch_bounds__(256) void sgemm_bias_kernel(
    const float* __restrict__ A, const float* __restrict__ Bm,
    const float* __restrict__ bias, float* __restrict__ C,
    int M, int Nn, int K)
{
    __shared__ float As[8][128];
    __shared__ float Bs[8][128];
    const int tid = threadIdx.x;
    const int bx = blockIdx.x, by = blockIdx.y;
    const int tx = tid & 15, ty = tid >> 4;
    const int la_r = tid >> 1, la_c = (tid & 1) * 4;
    const int lb_r = tid >> 5, lb_c = (tid & 31) * 4;

    const float* Ap = A + (size_t)(by * 128 + la_r) * K + la_c;
    const float* Bp = Bm + (size_t)lb_r * Nn + bx * 128 + lb_c;

    float acc[8][8] = {};
    for (int k0 = 0; k0 < K; k0 += 8) {
        float4 a4 = *(const float4*)(Ap + k0);
        float4 b4 = *(const float4*)(Bp + (size_t)k0 * Nn);
        As[la_c + 0][la_r] = a4.x; As[la_c + 1][la_r] = a4.y;
        As[la_c + 2][la_r] = a4.z; As[la_c + 3][la_r] = a4.w;
        *(float4*)&Bs[lb_r][lb_c] = b4;
        __syncthreads();
        #pragma unroll
        for (int kk = 0; kk < 8; kk++) {
            float ar[8], br[8];
            #pragma unroll
            for (int i = 0; i < 8; i++) ar[i] = As[kk][ty * 8 + i];
            #pragma unroll
            for (int j = 0; j < 8; j++) br[j] = Bs[kk][tx * 8 + j];
            #pragma unroll
            for (int i = 0; i < 8; i++)
                #pragma unroll
                for (int j = 0; j < 8; j++)
                    acc[i][j] = fmaf(ar[i], br[j], acc[i][j]);
        }
        __syncthreads();
    }

    float bv[8];
    #pragma unroll
    for (int j = 0; j < 8; j++) bv[j] = bias ? bias[bx * 128 + tx * 8 + j] : 0.0f;
    #pragma unroll
    for (int i = 0; i < 8; i++) {
        size_t roff = (size_t)(by * 128 + ty * 8 + i) * Nn + bx * 128 + tx * 8;
        float4 o0 = make_float4(acc[i][0] + bv[0], acc[i][1] + bv[1],
                                acc[i][2] + bv[2], acc[i][3] + bv[3]);
        float4 o1 = make_float4(acc[i][4] + bv[4], acc[i][5] + bv[5],
                                acc[i][6] + bv[6], acc[i][7] + bv[7]);
        *(float4*)(C + roff)     = o0;
        *(float4*)(C + roff + 4) = o1;
    }
}

// ---------------------------------------------------------------------------
// fp32 scores (decision-critical): S = SCALE * q . k^T
// R1 kernel + fused per-row tile stats (max, sumexp) epilogue.
// Thread (ty,tx) owns rows ty*8+i, cols tx*8+j; lanes sharing ty are a
// 16-lane subgroup of one warp -> shfl_xor(8,4,2,1) reduces over the tile row.
// ---------------------------------------------------------------------------
__global__ __launch_bounds__(256) void scores_kernel(float* __restrict__ S)
{
    __shared__ float Qs[8][128];
    __shared__ float Ks[8][128];
    const int tid = threadIdx.x;
    const int bx = blockIdx.x;   // j tile
    const int by = blockIdx.y;   // i tile
    const int bh = blockIdx.z;
    const int b = bh >> 3, h = bh & 7;
    const int tx = tid & 15, ty = tid >> 4;
    const int lr = tid >> 1, lc = (tid & 1) * 4;

    const float* qbase = g_qkv + (size_t)b * NSEQ * QKVN + h * DHEAD;
    const float* qp = qbase + (size_t)(by * 128 + lr) * QKVN + lc;
    const float* kp = qbase + INNER + (size_t)(bx * 128 + lr) * QKVN + lc;

    float acc[8][8] = {};
    for (int d0 = 0; d0 < DHEAD; d0 += 8) {
        float4 q4 = *(const float4*)(qp + d0);
        float4 k4 = *(const float4*)(kp + d0);
        Qs[lc + 0][lr] = q4.x; Qs[lc + 1][lr] = q4.y;
        Qs[lc + 2][lr] = q4.z; Qs[lc + 3][lr] = q4.w;
        Ks[lc + 0][lr] = k4.x; Ks[lc + 1][lr] = k4.y;
        Ks[lc + 2][lr] = k4.z; Ks[lc + 3][lr] = k4.w;
        __syncthreads();
        #pragma unroll
        for (int kk = 0; kk < 8; kk++) {
            float ar[8], br[8];
            #pragma unroll
            for (int i = 0; i < 8; i++) ar[i] = Qs[kk][ty * 8 + i];
            #pragma unroll
            for (int j = 0; j < 8; j++) br[j] = Ks[kk][tx * 8 + j];
            #pragma unroll
            for (int i = 0; i < 8; i++)
                #pragma unroll
                for (int j = 0; j < 8; j++)
                    acc[i][j] = fmaf(ar[i], br[j], acc[i][j]);
        }
        __syncthreads();
    }

    float* Sp = S + ((size_t)bh * NSEQ + by * 128 + ty * 8) * NSEQ + bx * 128 + tx * 8;
    #pragma unroll
    for (int i = 0; i < 8; i++) {
        float z[8];
        #pragma unroll
        for (int j = 0; j < 8; j++) z[j] = acc[i][j] * SCALE;
        *(float4*)(Sp + (size_t)i * NSEQ)     = make_float4(z[0], z[1], z[2], z[3]);
        *(float4*)(Sp + (size_t)i * NSEQ + 4) = make_float4(z[4], z[5], z[6], z[7]);

        // per-(row, jtile) stats
        float m = z[0];
        #pragma unroll
        for (int j = 1; j < 8; j++) m = fmaxf(m, z[j]);
        #pragma unroll
        for (int o = 8; o > 0; o >>= 1)
            m = fmaxf(m, __shfl_xor_sync(0xffffffffu, m, o));
        float s = 0.0f;
        #pragma unroll
        for (int j = 0; j < 8; j++) s += __expf(z[j] - m);
        #pragma unroll
        for (int o = 8; o > 0; o >>= 1)
            s += __shfl_xor_sync(0xffffffffu, s, o);
        if (tx == 0) {
            size_t row = (size_t)bh * NSEQ + by * 128 + ty * 8 + i;
            g_part[row * 16 + bx] = make_float2(m, s);
        }
    }
}

// ---------------------------------------------------------------------------
// Select: one block per attention row.
// Combine 16 tile partials -> exact (m, Z); stream the row of S; append
// surviving (col, p) pairs (p = exp(z-m)/Z > THRESH) to a compact list.
// ---------------------------------------------------------------------------
__global__ __launch_bounds__(256) void select_kernel(const float* __restrict__ S)
{
    const size_t row = blockIdx.x;
    const int t = threadIdx.x;
    __shared__ float sm, sinv;
    __shared__ int   cnt;
    __shared__ int   cols_s[MAXS];
    __shared__ float vals_s[MAXS];

    if (t == 0) {
        cnt = 0;
        float2 p0 = g_part[row * 16];
        float m = p0.x;
        #pragma unroll
        for (int k = 1; k < 16; k++) m = fmaxf(m, g_part[row * 16 + k].x);
        float Z = 0.0f;
        #pragma unroll
        for (int k = 0; k < 16; k++) {
            float2 pk = g_part[row * 16 + k];
            Z += pk.y * __expf(pk.x - m);
        }
        sm = m; sinv = 1.0f / Z;
    }
    __syncthreads();
    const float m = sm, inv = sinv;

    const float* p = S + row * NSEQ;
    #pragma unroll
    for (int c0 = 0; c0 < NSEQ; c0 += 256) {
        float z = p[c0 + t];
        float pv = __expf(z - m) * inv;
        if (pv > THRESH) {
            int idx = atomicAdd(&cnt, 1);
            if (idx < MAXS) { cols_s[idx] = c0 + t; vals_s[idx] = pv; }
        }
    }
    __syncthreads();
    int n = cnt < MAXS ? cnt : MAXS;
    if (t == 0) g_cnt[row] = n;
    if (t < n) {
        g_cols[row * MAXS + t] = cols_s[t];
        g_vals[row * MAXS + t] = vals_s[t];
    }
}

// ---------------------------------------------------------------------------
// Sparse PV: one warp per attention row. ctx[row] = sum_k p_k * V[col_k].
// ---------------------------------------------------------------------------
__global__ __launch_bounds__(256) void spv_kernel()
{
    const size_t w = ((size_t)blockIdx.x * blockDim.x + threadIdx.x) >> 5;
    const int lane = threadIdx.x & 31;
    if (w >= NROWS) return;
    const int bh = (int)(w >> 11), i = (int)(w & 2047);
    const int b = bh >> 3, h = bh & 7;

    const float* Vb = g_qkv + (size_t)b * NSEQ * QKVN + 2 * INNER + h * DHEAD;
    const int n = g_cnt[w];
    float a0 = 0.0f, a1 = 0.0f;
    for (int k = 0; k < n; k++) {
        int   c  = g_cols[w * MAXS + k];
        float pv = g_vals[w * MAXS + k];
        const float* v = Vb + (size_t)c * QKVN;
        a0 = fmaf(pv, v[lane],      a0);
        a1 = fmaf(pv, v[lane + 32], a1);
    }
    float* o = g_ctx + ((size_t)b * NSEQ + i) * INNER + h * DHEAD;
    o[lane]      = a0;
    o[lane + 32] = a1;
}

// ---------------------------------------------------------------------------
// 3xTF32 helpers (smooth path)
// ---------------------------------------------------------------------------
__device__ __forceinline__ void split_tf32(float x, uint32_t& hi, uint32_t& lo) {
    uint32_t h;
    asm("cvt.rna.tf32.f32 %0, %1;" : "=r"(h) : "f"(x));
    float hf = __uint_as_float(h);
    asm("cvt.rna.tf32.f32 %0, %1;" : "=r"(lo) : "f"(x - hf));
    hi = h;
}
__device__ __forceinline__ void mma8(float* c, const uint32_t* a, const uint32_t* b) {
    asm volatile(
        "mma.sync.aligned.m16n8k8.row.col.f32.tf32.tf32.f32 "
        "{%0,%1,%2,%3},{%4,%5,%6,%7},{%8,%9},{%0,%1,%2,%3};"
        : "+f"(c[0]), "+f"(c[1]), "+f"(c[2]), "+f"(c[3])
        : "r"(a[0]), "r"(a[1]), "r"(a[2]), "r"(a[3]), "r"(b[0]), "r"(b[1]));
}
__device__ __forceinline__ void mma3(float* c, const uint32_t* ah, const uint32_t* al,
                                     const uint32_t* bh, const uint32_t* bl) {
    mma8(c, ah, bh);
    mma8(c, ah, bl);
    mma8(c, al, bh);
}

// ---------------------------------------------------------------------------
// Out-proj (3xTF32): C[M,N] = A[M,K] @ B[K,N] + bias  (verbatim from R4)
// ---------------------------------------------------------------------------
__global__ __launch_bounds__(256) void sgemm_mma_bias(
    const float* __restrict__ A, const float* __restrict__ Bm,
    const float* __restrict__ bias, float* __restrict__ C,
    int M, int N, int K)
{
    __shared__ uint32_t As[2][16][136];
    __shared__ uint32_t Bs[2][16][136];
    const int tid = threadIdx.x;
    const int bx = blockIdx.x, by = blockIdx.y;
    const int lane = tid & 31, wid = tid >> 5;
    const int gid = lane >> 2, tig = lane & 3;
    const int wm = wid & 1, wn = wid >> 1;
    const int ar = tid >> 2, aq = tid & 3;
    const int bkr = tid >> 4, bc = (tid & 15) * 8;

    const float* Ap0 = A + (size_t)(by * 128 + ar) * K + aq * 4;
    const float* Ap1 = Ap0 + (size_t)64 * K;
    const float* Bp  = Bm + (size_t)bkr * N + bx * 128 + bc;

    float4 av0 = *(const float4*)Ap0;
    float4 av1 = *(const float4*)Ap1;
    float4 bv0 = *(const float4*)Bp;
    float4 bv1 = *(const float4*)(Bp + 4);

    float acc[4][4][4] = {};

    for (int k0 = 0; k0 < K; k0 += 16) {
        const float* a0 = &av0.x; const float* a1 = &av1.x;
        #pragma unroll
        for (int e = 0; e < 4; e++) {
            uint32_t h, l;
            split_tf32(a0[e], h, l);
            As[0][aq * 4 + e][ar] = h; As[1][aq * 4 + e][ar] = l;
            split_tf32(a1[e], h, l);
            As[0][aq * 4 + e][ar + 64] = h; As[1][aq * 4 + e][ar + 64] = l;
        }
        const float* b0p = &bv0.x; const float* b1p = &bv1.x;
        #pragma unroll
        for (int e = 0; e < 4; e++) {
            uint32_t h, l;
            split_tf32(b0p[e], h, l);
            Bs[0][bkr][bc + e] = h; Bs[1][bkr][bc + e] = l;
            split_tf32(b1p[e], h, l);
            Bs[0][bkr][bc + 4 + e] = h; Bs[1][bkr][bc + 4 + e] = l;
        }
        __syncthreads();

        if (k0 + 16 < K) {
            av0 = *(const float4*)(Ap0 + k0 + 16);
            av1 = *(const float4*)(Ap1 + k0 + 16);
            bv0 = *(const float4*)(Bp + (size_t)(k0 + 16) * N);
            bv1 = *(const float4*)(Bp + (size_t)(k0 + 16) * N + 4);
        }

        #pragma unroll
        for (int ks = 0; ks < 16; ks += 8) {
            uint32_t afh[4][4], afl[4][4], bfh[4][2], bfl[4][2];
            #pragma unroll
            for (int i = 0; i < 4; i++) {
                int m0 = wm * 64 + i * 16;
                afh[i][0] = As[0][ks + tig][m0 + gid];
                afh[i][1] = As[0][ks + tig][m0 + gid + 8];
                afh[i][2] = As[0][ks + tig + 4][m0 + gid];
                afh[i][3] = As[0][ks + tig + 4][m0 + gid + 8];
                afl[i][0] = As[1][ks + tig][m0 + gid];
                afl[i][1] = As[1][ks + tig][m0 + gid + 8];
                afl[i][2] = As[1][ks + tig + 4][m0 + gid];
                afl[i][3] = As[1][ks + tig + 4][m0 + gid + 8];
            }
            #pragma unroll
            for (int j = 0; j < 4; j++) {
                int n0 = wn * 32 + j * 8;
                bfh[j][0] = Bs[0][ks + tig][n0 + gid];
                bfh[j][1] = Bs[0][ks + tig + 4][n0 + gid];
                bfl[j][0] = Bs[1][ks + tig][n0 + gid];
                bfl[j][1] = Bs[1][ks + tig + 4][n0 + gid];
            }
            #pragma unroll
            for (int i = 0; i < 4; i++)
                #pragma unroll
                for (int j = 0; j < 4; j++)
                    mma3(acc[i][j], afh[i], afl[i], bfh[j], bfl[j]);
        }
        __syncthreads();
    }

    #pragma unroll
    for (int i = 0; i < 4; i++) {
        int row = by * 128 + wm * 64 + i * 16 + gid;
        #pragma unroll
        for (int j = 0; j < 4; j++) {
            int col = bx * 128 + wn * 32 + j * 8 + tig * 2;
            float b0 = bias ? bias[col] : 0.f;
            float b1 = bias ? bias[col + 1] : 0.f;
            *(float2*)(C + (size_t)row * N + col) =
                make_float2(acc[i][j][0] + b0, acc[i][j][1] + b1);
            *(float2*)(C + (size_t)(row + 8) * N + col) =
                make_float2(acc[i][j][2] + b0, acc[i][j][3] + b1);
        }
    }
}

// ---------------------------------------------------------------------------
extern "C" void kernel_launch(void* const* d_in, const int* in_sizes, int n_in,
                              void* d_out, int out_size)
{
    const float* x    = (const float*)d_in[0];
    const float* Wqkv = (const float*)d_in[1];
    const float* bqkv = (const float*)d_in[2];
    const float* Wout = (const float*)d_in[3];
    const float* bout = (const float*)d_in[4];
    float* out = (float*)d_out;

    float *qkv_ptr, *sc_ptr, *ctx_ptr;
    cudaGetSymbolAddress((void**)&qkv_ptr, g_qkv);
    cudaGetSymbolAddress((void**)&sc_ptr,  g_scores);
    cudaGetSymbolAddress((void**)&ctx_ptr, g_ctx);

    // 1) QKV projection (fp32, decision-critical)
    sgemm_bias_kernel<<<dim3(QKVN / 128, (BATCH * NSEQ) / 128), 256>>>(
        x, Wqkv, bqkv, qkv_ptr, BATCH * NSEQ, QKVN, DIM);

    // 2) Attention scores (fp32) + fused per-tile row stats
    scores_kernel<<<dim3(NSEQ / 128, NSEQ / 128, BATCH * HEADS), 256>>>(sc_ptr);

    // 3) Combine stats + select surviving attention entries (sparse!)
    select_kernel<<<(int)NROWS, 256>>>(sc_ptr);

    // 4) Sparse P@V (one warp per row; ~0.4 survivors/row)
    spv_kernel<<<(int)(NROWS * 32 / 256), 256>>>();

    // 5) Output projection (3xTF32 tensor path)
    sgemm_mma_bias<<<dim3(INNER / 128, (BATCH * NSEQ) / 128), 256>>>(
        ctx_ptr, Wout, bout, out, BATCH * NSEQ, INNER, INNER);
}

// round 6
// speedup vs baseline: 1.5418x; 1.0804x over previous
#include <cuda_runtime.h>
#include <cstdint>

// Problem constants
#define BATCH   4
#define NSEQ    2048
#define DIM     512
#define HEADS   8
#define DHEAD   64
#define INNER   512          // HEADS*DHEAD
#define QKVN    1536         // 3*INNER
#define SCALE   0.125f       // 64^-0.5
#define THRESH  0.01f
#define NROWS   ((size_t)BATCH * HEADS * NSEQ)   // 65536 attention rows
#define MAXS    32                                // survivor slots per row

// Scratch (device globals: allocation-free per harness rules)
__device__ float  g_qkv[(size_t)BATCH * NSEQ * QKVN];                // 50.3 MB
__device__ float  g_scores[(size_t)BATCH * HEADS * NSEQ * NSEQ];     // 537 MB
__device__ float  g_ctx[(size_t)BATCH * NSEQ * INNER];               // 16.8 MB
__device__ float2 g_part[NROWS * 16];                                // per (row, jtile) (max, sumexp)
__device__ int    g_cnt[NROWS];
__device__ int    g_cols[NROWS * MAXS];
__device__ float  g_vals[NROWS * MAXS];

// ---------------------------------------------------------------------------
// fp32 SGEMM, double-buffered: C[M,N] = A[M,K] @ B[K,N] + bias[N]
// 128x128 tile, BK=8, 256 threads, 8x8 per thread. One sync per k-chunk.
// ---------------------------------------------------------------------------
__global__ __launch_bounds__(256) void sgemm_bias_kernel(
    const float* __restrict__ A, const float* __restrict__ Bm,
    const float* __restrict__ bias, float* __restrict__ C,
    int M, int Nn, int K)
{
    __shared__ float As[2][8][128];
    __shared__ float Bs[2][8][128];
    const int tid = threadIdx.x;
    const int bx = blockIdx.x, by = blockIdx.y;
    const int tx = tid & 15, ty = tid >> 4;
    const int la_r = tid >> 1, la_c = (tid & 1) * 4;
    const int lb_r = tid >> 5, lb_c = (tid & 31) * 4;

    const float* Ap = A + (size_t)(by * 128 + la_r) * K + la_c;
    const float* Bp = Bm + (size_t)lb_r * Nn + bx * 128 + lb_c;

    float4 a4 = *(const float4*)Ap;
    float4 b4 = *(const float4*)Bp;
    As[0][la_c + 0][la_r] = a4.x; As[0][la_c + 1][la_r] = a4.y;
    As[0][la_c + 2][la_r] = a4.z; As[0][la_c + 3][la_r] = a4.w;
    *(float4*)&Bs[0][lb_r][lb_c] = b4;
    __syncthreads();

    float acc[8][8] = {};
    int cur = 0;
    for (int k0 = 0; k0 < K; k0 += 8) {
        const bool nxt = (k0 + 8 < K);
        if (nxt) {
            a4 = *(const float4*)(Ap + k0 + 8);
            b4 = *(const float4*)(Bp + (size_t)(k0 + 8) * Nn);
        }
        #pragma unroll
        for (int kk = 0; kk < 8; kk++) {
            float ar[8], br[8];
            #pragma unroll
            for (int i = 0; i < 8; i++) ar[i] = As[cur][kk][ty * 8 + i];
            #pragma unroll
            for (int j = 0; j < 8; j++) br[j] = Bs[cur][kk][tx * 8 + j];
            #pragma unroll
            for (int i = 0; i < 8; i++)
                #pragma unroll
                for (int j = 0; j < 8; j++)
                    acc[i][j] = fmaf(ar[i], br[j], acc[i][j]);
        }
        if (nxt) {
            int b2 = cur ^ 1;
            As[b2][la_c + 0][la_r] = a4.x; As[b2][la_c + 1][la_r] = a4.y;
            As[b2][la_c + 2][la_r] = a4.z; As[b2][la_c + 3][la_r] = a4.w;
            *(float4*)&Bs[b2][lb_r][lb_c] = b4;
            __syncthreads();
            cur = b2;
        }
    }

    float bv[8];
    #pragma unroll
    for (int j = 0; j < 8; j++) bv[j] = bias ? bias[bx * 128 + tx * 8 + j] : 0.0f;
    #pragma unroll
    for (int i = 0; i < 8; i++) {
        size_t roff = (size_t)(by * 128 + ty * 8 + i) * Nn + bx * 128 + tx * 8;
        float4 o0 = make_float4(acc[i][0] + bv[0], acc[i][1] + bv[1],
                                acc[i][2] + bv[2], acc[i][3] + bv[3]);
        float4 o1 = make_float4(acc[i][4] + bv[4], acc[i][5] + bv[5],
                                acc[i][6] + bv[6], acc[i][7] + bv[7]);
        *(float4*)(C + roff)     = o0;
        *(float4*)(C + roff + 4) = o1;
    }
}

// ---------------------------------------------------------------------------
// fp32 scores, double-buffered: S = SCALE * q . k^T + fused per-tile row stats.
// ---------------------------------------------------------------------------
__global__ __launch_bounds__(256) void scores_kernel(float* __restrict__ S)
{
    __shared__ float Qs[2][8][128];
    __shared__ float Ks[2][8][128];
    const int tid = threadIdx.x;
    const int bx = blockIdx.x;   // j tile
    const int by = blockIdx.y;   // i tile
    const int bh = blockIdx.z;
    const int b = bh >> 3, h = bh & 7;
    const int tx = tid & 15, ty = tid >> 4;
    const int lr = tid >> 1, lc = (tid & 1) * 4;

    const float* qbase = g_qkv + (size_t)b * NSEQ * QKVN + h * DHEAD;
    const float* qp = qbase + (size_t)(by * 128 + lr) * QKVN + lc;
    const float* kp = qbase + INNER + (size_t)(bx * 128 + lr) * QKVN + lc;

    float4 q4 = *(const float4*)qp;
    float4 k4 = *(const float4*)kp;
    Qs[0][lc + 0][lr] = q4.x; Qs[0][lc + 1][lr] = q4.y;
    Qs[0][lc + 2][lr] = q4.z; Qs[0][lc + 3][lr] = q4.w;
    Ks[0][lc + 0][lr] = k4.x; Ks[0][lc + 1][lr] = k4.y;
    Ks[0][lc + 2][lr] = k4.z; Ks[0][lc + 3][lr] = k4.w;
    __syncthreads();

    float acc[8][8] = {};
    int cur = 0;
    for (int d0 = 0; d0 < DHEAD; d0 += 8) {
        const bool nxt = (d0 + 8 < DHEAD);
        if (nxt) {
            q4 = *(const float4*)(qp + d0 + 8);
            k4 = *(const float4*)(kp + d0 + 8);
        }
        #pragma unroll
        for (int kk = 0; kk < 8; kk++) {
            float ar[8], br[8];
            #pragma unroll
            for (int i = 0; i < 8; i++) ar[i] = Qs[cur][kk][ty * 8 + i];
            #pragma unroll
            for (int j = 0; j < 8; j++) br[j] = Ks[cur][kk][tx * 8 + j];
            #pragma unroll
            for (int i = 0; i < 8; i++)
                #pragma unroll
                for (int j = 0; j < 8; j++)
                    acc[i][j] = fmaf(ar[i], br[j], acc[i][j]);
        }
        if (nxt) {
            int b2 = cur ^ 1;
            Qs[b2][lc + 0][lr] = q4.x; Qs[b2][lc + 1][lr] = q4.y;
            Qs[b2][lc + 2][lr] = q4.z; Qs[b2][lc + 3][lr] = q4.w;
            Ks[b2][lc + 0][lr] = k4.x; Ks[b2][lc + 1][lr] = k4.y;
            Ks[b2][lc + 2][lr] = k4.z; Ks[b2][lc + 3][lr] = k4.w;
            __syncthreads();
            cur = b2;
        }
    }

    float* Sp = S + ((size_t)bh * NSEQ + by * 128 + ty * 8) * NSEQ + bx * 128 + tx * 8;
    #pragma unroll
    for (int i = 0; i < 8; i++) {
        float z[8];
        #pragma unroll
        for (int j = 0; j < 8; j++) z[j] = acc[i][j] * SCALE;
        *(float4*)(Sp + (size_t)i * NSEQ)     = make_float4(z[0], z[1], z[2], z[3]);
        *(float4*)(Sp + (size_t)i * NSEQ + 4) = make_float4(z[4], z[5], z[6], z[7]);

        // per-(row, jtile) stats: 16 lanes sharing ty reduce over 128 cols
        float m = z[0];
        #pragma unroll
        for (int j = 1; j < 8; j++) m = fmaxf(m, z[j]);
        #pragma unroll
        for (int o = 8; o > 0; o >>= 1)
            m = fmaxf(m, __shfl_xor_sync(0xffffffffu, m, o));
        float s = 0.0f;
        #pragma unroll
        for (int j = 0; j < 8; j++) s += __expf(z[j] - m);
        #pragma unroll
        for (int o = 8; o > 0; o >>= 1)
            s += __shfl_xor_sync(0xffffffffu, s, o);
        if (tx == 0) {
            size_t row = (size_t)bh * NSEQ + by * 128 + ty * 8 + i;
            g_part[row * 16 + bx] = make_float2(m, s);
        }
    }
}

// ---------------------------------------------------------------------------
// Select: one block per attention row.
// Warp 0 combines 16 tile partials -> exact (m, Z) and a log-domain cutoff
// zcut (with conservative margin). Scan is pure float4 compare; __expf only
// for the rare candidates; final inclusion = exact R5 check.
// ---------------------------------------------------------------------------
__global__ __launch_bounds__(256) void select_kernel(const float* __restrict__ S)
{
    const size_t row = blockIdx.x;
    const int t = threadIdx.x;
    __shared__ float sm, sinv, szcut;
    __shared__ int   cnt;
    __shared__ int   cols_s[MAXS];
    __shared__ float vals_s[MAXS];

    if (t < 32) {
        float2 pk = (t < 16) ? g_part[row * 16 + t] : make_float2(-1e30f, 0.0f);
        float m = pk.x;
        #pragma unroll
        for (int o = 8; o > 0; o >>= 1)
            m = fmaxf(m, __shfl_xor_sync(0xffffffffu, m, o));
        float e = (t < 16) ? pk.y * __expf(pk.x - m) : 0.0f;
        #pragma unroll
        for (int o = 8; o > 0; o >>= 1)
            e += __shfl_xor_sync(0xffffffffu, e, o);
        if (t == 0) {
            sm = m; sinv = 1.0f / e;
            szcut = m + __logf(THRESH * e) - 1e-3f;   // conservative prefilter
            cnt = 0;
        }
    }
    __syncthreads();
    const float m = sm, inv = sinv, zcut = szcut;

    const float4* p4 = (const float4*)(S + row * NSEQ);
    #pragma unroll
    for (int it = 0; it < NSEQ / 1024; it++) {   // 2 iterations of 256 x float4
        float4 v = p4[it * 256 + t];
        int base = (it * 256 + t) * 4;
        float zs[4] = {v.x, v.y, v.z, v.w};
        #pragma unroll
        for (int e2 = 0; e2 < 4; e2++) {
            if (zs[e2] > zcut) {
                float pv = __expf(zs[e2] - m) * inv;
                if (pv > THRESH) {                    // exact check (R5 semantics)
                    int idx = atomicAdd(&cnt, 1);
                    if (idx < MAXS) { cols_s[idx] = base + e2; vals_s[idx] = pv; }
                }
            }
        }
    }
    __syncthreads();
    int n = cnt < MAXS ? cnt : MAXS;
    if (t == 0) g_cnt[row] = n;
    if (t < n) {
        g_cols[row * MAXS + t] = cols_s[t];
        g_vals[row * MAXS + t] = vals_s[t];
    }
}

// ---------------------------------------------------------------------------
// Sparse PV: one warp per attention row. ctx[row] = sum_k p_k * V[col_k].
// ---------------------------------------------------------------------------
__global__ __launch_bounds__(256) void spv_kernel()
{
    const size_t w = ((size_t)blockIdx.x * blockDim.x + threadIdx.x) >> 5;
    const int lane = threadIdx.x & 31;
    if (w >= NROWS) return;
    const int bh = (int)(w >> 11), i = (int)(w & 2047);
    const int b = bh >> 3, h = bh & 7;

    const float* Vb = g_qkv + (size_t)b * NSEQ * QKVN + 2 * INNER + h * DHEAD;
    const int n = g_cnt[w];
    float a0 = 0.0f, a1 = 0.0f;
    for (int k = 0; k < n; k++) {
        int   c  = g_cols[w * MAXS + k];
        float pv = g_vals[w * MAXS + k];
        const float* v = Vb + (size_t)c * QKVN;
        a0 = fmaf(pv, v[lane],      a0);
        a1 = fmaf(pv, v[lane + 32], a1);
    }
    float* o = g_ctx + ((size_t)b * NSEQ + i) * INNER + h * DHEAD;
    o[lane]      = a0;
    o[lane + 32] = a1;
}

// ---------------------------------------------------------------------------
// 3xTF32 helpers (smooth path)
// ---------------------------------------------------------------------------
__device__ __forceinline__ void split_tf32(float x, uint32_t& hi, uint32_t& lo) {
    uint32_t h;
    asm("cvt.rna.tf32.f32 %0, %1;" : "=r"(h) : "f"(x));
    float hf = __uint_as_float(h);
    asm("cvt.rna.tf32.f32 %0, %1;" : "=r"(lo) : "f"(x - hf));
    hi = h;
}
__device__ __forceinline__ void mma8(float* c, const uint32_t* a, const uint32_t* b) {
    asm volatile(
        "mma.sync.aligned.m16n8k8.row.col.f32.tf32.tf32.f32 "
        "{%0,%1,%2,%3},{%4,%5,%6,%7},{%8,%9},{%0,%1,%2,%3};"
        : "+f"(c[0]), "+f"(c[1]), "+f"(c[2]), "+f"(c[3])
        : "r"(a[0]), "r"(a[1]), "r"(a[2]), "r"(a[3]), "r"(b[0]), "r"(b[1]));
}
__device__ __forceinline__ void mma3(float* c, const uint32_t* ah, const uint32_t* al,
                                     const uint32_t* bh, const uint32_t* bl) {
    mma8(c, ah, bh);
    mma8(c, ah, bl);
    mma8(c, al, bh);
}

// ---------------------------------------------------------------------------
// Out-proj (3xTF32): C[M,N] = A[M,K] @ B[K,N] + bias  (verbatim from R4/R5)
// ---------------------------------------------------------------------------
__global__ __launch_bounds__(256) void sgemm_mma_bias(
    const float* __restrict__ A, const float* __restrict__ Bm,
    const float* __restrict__ bias, float* __restrict__ C,
    int M, int N, int K)
{
    __shared__ uint32_t As[2][16][136];
    __shared__ uint32_t Bs[2][16][136];
    const int tid = threadIdx.x;
    const int bx = blockIdx.x, by = blockIdx.y;
    const int lane = tid & 31, wid = tid >> 5;
    const int gid = lane >> 2, tig = lane & 3;
    const int wm = wid & 1, wn = wid >> 1;
    const int ar = tid >> 2, aq = tid & 3;
    const int bkr = tid >> 4, bc = (tid & 15) * 8;

    const float* Ap0 = A + (size_t)(by * 128 + ar) * K + aq * 4;
    const float* Ap1 = Ap0 + (size_t)64 * K;
    const float* Bp  = Bm + (size_t)bkr * N + bx * 128 + bc;

    float4 av0 = *(const float4*)Ap0;
    float4 av1 = *(const float4*)Ap1;
    float4 bv0 = *(const float4*)Bp;
    float4 bv1 = *(const float4*)(Bp + 4);

    float acc[4][4][4] = {};

    for (int k0 = 0; k0 < K; k0 += 16) {
        const float* a0 = &av0.x; const float* a1 = &av1.x;
        #pragma unroll
        for (int e = 0; e < 4; e++) {
            uint32_t h, l;
            split_tf32(a0[e], h, l);
            As[0][aq * 4 + e][ar] = h; As[1][aq * 4 + e][ar] = l;
            split_tf32(a1[e], h, l);
            As[0][aq * 4 + e][ar + 64] = h; As[1][aq * 4 + e][ar + 64] = l;
        }
        const float* b0p = &bv0.x; const float* b1p = &bv1.x;
        #pragma unroll
        for (int e = 0; e < 4; e++) {
            uint32_t h, l;
            split_tf32(b0p[e], h, l);
            Bs[0][bkr][bc + e] = h; Bs[1][bkr][bc + e] = l;
            split_tf32(b1p[e], h, l);
            Bs[0][bkr][bc + 4 + e] = h; Bs[1][bkr][bc + 4 + e] = l;
        }
        __syncthreads();

        if (k0 + 16 < K) {
            av0 = *(const float4*)(Ap0 + k0 + 16);
            av1 = *(const float4*)(Ap1 + k0 + 16);
            bv0 = *(const float4*)(Bp + (size_t)(k0 + 16) * N);
            bv1 = *(const float4*)(Bp + (size_t)(k0 + 16) * N + 4);
        }

        #pragma unroll
        for (int ks = 0; ks < 16; ks += 8) {
            uint32_t afh[4][4], afl[4][4], bfh[4][2], bfl[4][2];
            #pragma unroll
            for (int i = 0; i < 4; i++) {
                int m0 = wm * 64 + i * 16;
                afh[i][0] = As[0][ks + tig][m0 + gid];
                afh[i][1] = As[0][ks + tig][m0 + gid + 8];
                afh[i][2] = As[0][ks + tig + 4][m0 + gid];
                afh[i][3] = As[0][ks + tig + 4][m0 + gid + 8];
                afl[i][0] = As[1][ks + tig][m0 + gid];
                afl[i][1] = As[1][ks + tig][m0 + gid + 8];
                afl[i][2] = As[1][ks + tig + 4][m0 + gid];
                afl[i][3] = As[1][ks + tig + 4][m0 + gid + 8];
            }
            #pragma unroll
            for (int j = 0; j < 4; j++) {
                int n0 = wn * 32 + j * 8;
                bfh[j][0] = Bs[0][ks + tig][n0 + gid];
                bfh[j][1] = Bs[0][ks + tig + 4][n0 + gid];
                bfl[j][0] = Bs[1][ks + tig][n0 + gid];
                bfl[j][1] = Bs[1][ks + tig + 4][n0 + gid];
            }
            #pragma unroll
            for (int i = 0; i < 4; i++)
                #pragma unroll
                for (int j = 0; j < 4; j++)
                    mma3(acc[i][j], afh[i], afl[i], bfh[j], bfl[j]);
        }
        __syncthreads();
    }

    #pragma unroll
    for (int i = 0; i < 4; i++) {
        int row = by * 128 + wm * 64 + i * 16 + gid;
        #pragma unroll
        for (int j = 0; j < 4; j++) {
            int col = bx * 128 + wn * 32 + j * 8 + tig * 2;
            float b0 = bias ? bias[col] : 0.f;
            float b1 = bias ? bias[col + 1] : 0.f;
            *(float2*)(C + (size_t)row * N + col) =
                make_float2(acc[i][j][0] + b0, acc[i][j][1] + b1);
            *(float2*)(C + (size_t)(row + 8) * N + col) =
                make_float2(acc[i][j][2] + b0, acc[i][j][3] + b1);
        }
    }
}

// ---------------------------------------------------------------------------
extern "C" void kernel_launch(void* const* d_in, const int* in_sizes, int n_in,
                              void* d_out, int out_size)
{
    const float* x    = (const float*)d_in[0];
    const float* Wqkv = (const float*)d_in[1];
    const float* bqkv = (const float*)d_in[2];
    const float* Wout = (const float*)d_in[3];
    const float* bout = (const float*)d_in[4];
    float* out = (float*)d_out;

    float *qkv_ptr, *sc_ptr, *ctx_ptr;
    cudaGetSymbolAddress((void**)&qkv_ptr, g_qkv);
    cudaGetSymbolAddress((void**)&sc_ptr,  g_scores);
    cudaGetSymbolAddress((void**)&ctx_ptr, g_ctx);

    // 1) QKV projection (fp32, decision-critical, double-buffered)
    sgemm_bias_kernel<<<dim3(QKVN / 128, (BATCH * NSEQ) / 128), 256>>>(
        x, Wqkv, bqkv, qkv_ptr, BATCH * NSEQ, QKVN, DIM);

    // 2) Attention scores (fp32, double-buffered) + fused per-tile row stats
    scores_kernel<<<dim3(NSEQ / 128, NSEQ / 128, BATCH * HEADS), 256>>>(sc_ptr);

    // 3) Combine stats + select surviving attention entries (log-domain scan)
    select_kernel<<<(int)NROWS, 256>>>(sc_ptr);

    // 4) Sparse P@V (one warp per row; ~0.4 survivors/row)
    spv_kernel<<<(int)(NROWS * 32 / 256), 256>>>();

    // 5) Output projection (3xTF32 tensor path)
    sgemm_mma_bias<<<dim3(INNER / 128, (BATCH * NSEQ) / 128), 256>>>(
        ctx_ptr, Wout, bout, out, BATCH * NSEQ, INNER, INNER);
}

// round 7
// speedup vs baseline: 1.5445x; 1.0017x over previous
#include <cuda_runtime.h>
#include <cstdint>

// Problem constants
#define BATCH   4
#define NSEQ    2048
#define DIM     512
#define HEADS   8
#define DHEAD   64
#define INNER   512          // HEADS*DHEAD
#define QKVN    1536         // 3*INNER
#define SCALE   0.125f       // 64^-0.5
#define THRESH  0.01f
#define NROWS   ((size_t)BATCH * HEADS * NSEQ)   // 65536 attention rows
#define MAXS    32                                // survivor slots per row

// Scratch (device globals: allocation-free per harness rules)
__device__ float  g_qkv[(size_t)BATCH * NSEQ * QKVN];                // 50.3 MB
__device__ float  g_scores[(size_t)BATCH * HEADS * NSEQ * NSEQ];     // 537 MB
__device__ float  g_ctx[(size_t)BATCH * NSEQ * INNER];               // 16.8 MB
__device__ float2 g_part[NROWS * 16];                                // per (row, jtile) (max, sumexp)
__device__ int    g_cnt[NROWS];
__device__ int    g_cols[NROWS * MAXS];
__device__ float  g_vals[NROWS * MAXS];

// ---------------------------------------------------------------------------
// fp32 SGEMM, double-buffered: C[M,N] = A[M,K] @ B[K,N] + bias[N]
// 128x128 tile, BK=8, 256 threads, 8x8 per thread. One sync per k-chunk.
// ---------------------------------------------------------------------------
__global__ __launch_bounds__(256) void sgemm_bias_kernel(
    const float* __restrict__ A, const float* __restrict__ Bm,
    const float* __restrict__ bias, float* __restrict__ C,
    int M, int Nn, int K)
{
    __shared__ float As[2][8][128];
    __shared__ float Bs[2][8][128];
    const int tid = threadIdx.x;
    const int bx = blockIdx.x, by = blockIdx.y;
    const int tx = tid & 15, ty = tid >> 4;
    const int la_r = tid >> 1, la_c = (tid & 1) * 4;
    const int lb_r = tid >> 5, lb_c = (tid & 31) * 4;

    const float* Ap = A + (size_t)(by * 128 + la_r) * K + la_c;
    const float* Bp = Bm + (size_t)lb_r * Nn + bx * 128 + lb_c;

    float4 a4 = *(const float4*)Ap;
    float4 b4 = *(const float4*)Bp;
    As[0][la_c + 0][la_r] = a4.x; As[0][la_c + 1][la_r] = a4.y;
    As[0][la_c + 2][la_r] = a4.z; As[0][la_c + 3][la_r] = a4.w;
    *(float4*)&Bs[0][lb_r][lb_c] = b4;
    __syncthreads();

    float acc[8][8] = {};
    int cur = 0;
    for (int k0 = 0; k0 < K; k0 += 8) {
        const bool nxt = (k0 + 8 < K);
        if (nxt) {
            a4 = *(const float4*)(Ap + k0 + 8);
            b4 = *(const float4*)(Bp + (size_t)(k0 + 8) * Nn);
        }
        #pragma unroll
        for (int kk = 0; kk < 8; kk++) {
            float ar[8], br[8];
            #pragma unroll
            for (int i = 0; i < 8; i++) ar[i] = As[cur][kk][ty * 8 + i];
            #pragma unroll
            for (int j = 0; j < 8; j++) br[j] = Bs[cur][kk][tx * 8 + j];
            #pragma unroll
            for (int i = 0; i < 8; i++)
                #pragma unroll
                for (int j = 0; j < 8; j++)
                    acc[i][j] = fmaf(ar[i], br[j], acc[i][j]);
        }
        if (nxt) {
            int b2 = cur ^ 1;
            As[b2][la_c + 0][la_r] = a4.x; As[b2][la_c + 1][la_r] = a4.y;
            As[b2][la_c + 2][la_r] = a4.z; As[b2][la_c + 3][la_r] = a4.w;
            *(float4*)&Bs[b2][lb_r][lb_c] = b4;
            __syncthreads();
            cur = b2;
        }
    }

    float bv[8];
    #pragma unroll
    for (int j = 0; j < 8; j++) bv[j] = bias ? bias[bx * 128 + tx * 8 + j] : 0.0f;
    #pragma unroll
    for (int i = 0; i < 8; i++) {
        size_t roff = (size_t)(by * 128 + ty * 8 + i) * Nn + bx * 128 + tx * 8;
        float4 o0 = make_float4(acc[i][0] + bv[0], acc[i][1] + bv[1],
                                acc[i][2] + bv[2], acc[i][3] + bv[3]);
        float4 o1 = make_float4(acc[i][4] + bv[4], acc[i][5] + bv[5],
                                acc[i][6] + bv[6], acc[i][7] + bv[7]);
        *(float4*)(C + roff)     = o0;
        *(float4*)(C + roff + 4) = o1;
    }
}

// ---------------------------------------------------------------------------
// fp32 scores, double-buffered: S = SCALE * q . k^T + fused per-tile row stats.
// ---------------------------------------------------------------------------
__global__ __launch_bounds__(256) void scores_kernel(float* __restrict__ S)
{
    __shared__ float Qs[2][8][128];
    __shared__ float Ks[2][8][128];
    const int tid = threadIdx.x;
    const int bx = blockIdx.x;   // j tile
    const int by = blockIdx.y;   // i tile
    const int bh = blockIdx.z;
    const int b = bh >> 3, h = bh & 7;
    const int tx = tid & 15, ty = tid >> 4;
    const int lr = tid >> 1, lc = (tid & 1) * 4;

    const float* qbase = g_qkv + (size_t)b * NSEQ * QKVN + h * DHEAD;
    const float* qp = qbase + (size_t)(by * 128 + lr) * QKVN + lc;
    const float* kp = qbase + INNER + (size_t)(bx * 128 + lr) * QKVN + lc;

    float4 q4 = *(const float4*)qp;
    float4 k4 = *(const float4*)kp;
    Qs[0][lc + 0][lr] = q4.x; Qs[0][lc + 1][lr] = q4.y;
    Qs[0][lc + 2][lr] = q4.z; Qs[0][lc + 3][lr] = q4.w;
    Ks[0][lc + 0][lr] = k4.x; Ks[0][lc + 1][lr] = k4.y;
    Ks[0][lc + 2][lr] = k4.z; Ks[0][lc + 3][lr] = k4.w;
    __syncthreads();

    float acc[8][8] = {};
    int cur = 0;
    for (int d0 = 0; d0 < DHEAD; d0 += 8) {
        const bool nxt = (d0 + 8 < DHEAD);
        if (nxt) {
            q4 = *(const float4*)(qp + d0 + 8);
            k4 = *(const float4*)(kp + d0 + 8);
        }
        #pragma unroll
        for (int kk = 0; kk < 8; kk++) {
            float ar[8], br[8];
            #pragma unroll
            for (int i = 0; i < 8; i++) ar[i] = Qs[cur][kk][ty * 8 + i];
            #pragma unroll
            for (int j = 0; j < 8; j++) br[j] = Ks[cur][kk][tx * 8 + j];
            #pragma unroll
            for (int i = 0; i < 8; i++)
                #pragma unroll
                for (int j = 0; j < 8; j++)
                    acc[i][j] = fmaf(ar[i], br[j], acc[i][j]);
        }
        if (nxt) {
            int b2 = cur ^ 1;
            Qs[b2][lc + 0][lr] = q4.x; Qs[b2][lc + 1][lr] = q4.y;
            Qs[b2][lc + 2][lr] = q4.z; Qs[b2][lc + 3][lr] = q4.w;
            Ks[b2][lc + 0][lr] = k4.x; Ks[b2][lc + 1][lr] = k4.y;
            Ks[b2][lc + 2][lr] = k4.z; Ks[b2][lc + 3][lr] = k4.w;
            __syncthreads();
            cur = b2;
        }
    }

    float* Sp = S + ((size_t)bh * NSEQ + by * 128 + ty * 8) * NSEQ + bx * 128 + tx * 8;
    #pragma unroll
    for (int i = 0; i < 8; i++) {
        float z[8];
        #pragma unroll
        for (int j = 0; j < 8; j++) z[j] = acc[i][j] * SCALE;
        *(float4*)(Sp + (size_t)i * NSEQ)     = make_float4(z[0], z[1], z[2], z[3]);
        *(float4*)(Sp + (size_t)i * NSEQ + 4) = make_float4(z[4], z[5], z[6], z[7]);

        // per-(row, jtile) stats: 16 lanes sharing ty reduce over 128 cols
        float m = z[0];
        #pragma unroll
        for (int j = 1; j < 8; j++) m = fmaxf(m, z[j]);
        #pragma unroll
        for (int o = 8; o > 0; o >>= 1)
            m = fmaxf(m, __shfl_xor_sync(0xffffffffu, m, o));
        float s = 0.0f;
        #pragma unroll
        for (int j = 0; j < 8; j++) s += __expf(z[j] - m);
        #pragma unroll
        for (int o = 8; o > 0; o >>= 1)
            s += __shfl_xor_sync(0xffffffffu, s, o);
        if (tx == 0) {
            size_t row = (size_t)bh * NSEQ + by * 128 + ty * 8 + i;
            g_part[row * 16 + bx] = make_float2(m, s);
        }
    }
}

// ---------------------------------------------------------------------------
// Select: one block per attention row.
// Warp 0 combines 16 tile partials -> exact (m, Z) and a log-domain cutoff
// zcut (with conservative margin). Scan is pure float4 compare; __expf only
// for the rare candidates; final inclusion = exact R5 check.
// ---------------------------------------------------------------------------
__global__ __launch_bounds__(256) void select_kernel(const float* __restrict__ S)
{
    const size_t row = blockIdx.x;
    const int t = threadIdx.x;
    __shared__ float sm, sinv, szcut;
    __shared__ int   cnt;
    __shared__ int   cols_s[MAXS];
    __shared__ float vals_s[MAXS];

    if (t < 32) {
        float2 pk = (t < 16) ? g_part[row * 16 + t] : make_float2(-1e30f, 0.0f);
        float m = pk.x;
        #pragma unroll
        for (int o = 8; o > 0; o >>= 1)
            m = fmaxf(m, __shfl_xor_sync(0xffffffffu, m, o));
        float e = (t < 16) ? pk.y * __expf(pk.x - m) : 0.0f;
        #pragma unroll
        for (int o = 8; o > 0; o >>= 1)
            e += __shfl_xor_sync(0xffffffffu, e, o);
        if (t == 0) {
            sm = m; sinv = 1.0f / e;
            szcut = m + __logf(THRESH * e) - 1e-3f;   // conservative prefilter
            cnt = 0;
        }
    }
    __syncthreads();
    const float m = sm, inv = sinv, zcut = szcut;

    const float4* p4 = (const float4*)(S + row * NSEQ);
    #pragma unroll
    for (int it = 0; it < NSEQ / 1024; it++) {   // 2 iterations of 256 x float4
        float4 v = p4[it * 256 + t];
        int base = (it * 256 + t) * 4;
        float zs[4] = {v.x, v.y, v.z, v.w};
        #pragma unroll
        for (int e2 = 0; e2 < 4; e2++) {
            if (zs[e2] > zcut) {
                float pv = __expf(zs[e2] - m) * inv;
                if (pv > THRESH) {                    // exact check (R5 semantics)
                    int idx = atomicAdd(&cnt, 1);
                    if (idx < MAXS) { cols_s[idx] = base + e2; vals_s[idx] = pv; }
                }
            }
        }
    }
    __syncthreads();
    int n = cnt < MAXS ? cnt : MAXS;
    if (t == 0) g_cnt[row] = n;
    if (t < n) {
        g_cols[row * MAXS + t] = cols_s[t];
        g_vals[row * MAXS + t] = vals_s[t];
    }
}

// ---------------------------------------------------------------------------
// Sparse PV: one warp per attention row. ctx[row] = sum_k p_k * V[col_k].
// ---------------------------------------------------------------------------
__global__ __launch_bounds__(256) void spv_kernel()
{
    const size_t w = ((size_t)blockIdx.x * blockDim.x + threadIdx.x) >> 5;
    const int lane = threadIdx.x & 31;
    if (w >= NROWS) return;
    const int bh = (int)(w >> 11), i = (int)(w & 2047);
    const int b = bh >> 3, h = bh & 7;

    const float* Vb = g_qkv + (size_t)b * NSEQ * QKVN + 2 * INNER + h * DHEAD;
    const int n = g_cnt[w];
    float a0 = 0.0f, a1 = 0.0f;
    for (int k = 0; k < n; k++) {
        int   c  = g_cols[w * MAXS + k];
        float pv = g_vals[w * MAXS + k];
        const float* v = Vb + (size_t)c * QKVN;
        a0 = fmaf(pv, v[lane],      a0);
        a1 = fmaf(pv, v[lane + 32], a1);
    }
    float* o = g_ctx + ((size_t)b * NSEQ + i) * INNER + h * DHEAD;
    o[lane]      = a0;
    o[lane + 32] = a1;
}

// ---------------------------------------------------------------------------
// 3xTF32 helpers (smooth path)
// ---------------------------------------------------------------------------
__device__ __forceinline__ void split_tf32(float x, uint32_t& hi, uint32_t& lo) {
    uint32_t h;
    asm("cvt.rna.tf32.f32 %0, %1;" : "=r"(h) : "f"(x));
    float hf = __uint_as_float(h);
    asm("cvt.rna.tf32.f32 %0, %1;" : "=r"(lo) : "f"(x - hf));
    hi = h;
}
__device__ __forceinline__ void mma8(float* c, const uint32_t* a, const uint32_t* b) {
    asm volatile(
        "mma.sync.aligned.m16n8k8.row.col.f32.tf32.tf32.f32 "
        "{%0,%1,%2,%3},{%4,%5,%6,%7},{%8,%9},{%0,%1,%2,%3};"
        : "+f"(c[0]), "+f"(c[1]), "+f"(c[2]), "+f"(c[3])
        : "r"(a[0]), "r"(a[1]), "r"(a[2]), "r"(a[3]), "r"(b[0]), "r"(b[1]));
}
__device__ __forceinline__ void mma3(float* c, const uint32_t* ah, const uint32_t* al,
                                     const uint32_t* bh, const uint32_t* bl) {
    mma8(c, ah, bh);
    mma8(c, ah, bl);
    mma8(c, al, bh);
}

// ---------------------------------------------------------------------------
// Out-proj (3xTF32): C[M,N] = A[M,K] @ B[K,N] + bias  (verbatim from R4/R5)
// ---------------------------------------------------------------------------
__global__ __launch_bounds__(256) void sgemm_mma_bias(
    const float* __restrict__ A, const float* __restrict__ Bm,
    const float* __restrict__ bias, float* __restrict__ C,
    int M, int N, int K)
{
    __shared__ uint32_t As[2][16][136];
    __shared__ uint32_t Bs[2][16][136];
    const int tid = threadIdx.x;
    const int bx = blockIdx.x, by = blockIdx.y;
    const int lane = tid & 31, wid = tid >> 5;
    const int gid = lane >> 2, tig = lane & 3;
    const int wm = wid & 1, wn = wid >> 1;
    const int ar = tid >> 2, aq = tid & 3;
    const int bkr = tid >> 4, bc = (tid & 15) * 8;

    const float* Ap0 = A + (size_t)(by * 128 + ar) * K + aq * 4;
    const float* Ap1 = Ap0 + (size_t)64 * K;
    const float* Bp  = Bm + (size_t)bkr * N + bx * 128 + bc;

    float4 av0 = *(const float4*)Ap0;
    float4 av1 = *(const float4*)Ap1;
    float4 bv0 = *(const float4*)Bp;
    float4 bv1 = *(const float4*)(Bp + 4);

    float acc[4][4][4] = {};

    for (int k0 = 0; k0 < K; k0 += 16) {
        const float* a0 = &av0.x; const float* a1 = &av1.x;
        #pragma unroll
        for (int e = 0; e < 4; e++) {
            uint32_t h, l;
            split_tf32(a0[e], h, l);
            As[0][aq * 4 + e][ar] = h; As[1][aq * 4 + e][ar] = l;
            split_tf32(a1[e], h, l);
            As[0][aq * 4 + e][ar + 64] = h; As[1][aq * 4 + e][ar + 64] = l;
        }
        const float* b0p = &bv0.x; const float* b1p = &bv1.x;
        #pragma unroll
        for (int e = 0; e < 4; e++) {
            uint32_t h, l;
            split_tf32(b0p[e], h, l);
            Bs[0][bkr][bc + e] = h; Bs[1][bkr][bc + e] = l;
            split_tf32(b1p[e], h, l);
            Bs[0][bkr][bc + 4 + e] = h; Bs[1][bkr][bc + 4 + e] = l;
        }
        __syncthreads();

        if (k0 + 16 < K) {
            av0 = *(const float4*)(Ap0 + k0 + 16);
            av1 = *(const float4*)(Ap1 + k0 + 16);
            bv0 = *(const float4*)(Bp + (size_t)(k0 + 16) * N);
            bv1 = *(const float4*)(Bp + (size_t)(k0 + 16) * N + 4);
        }

        #pragma unroll
        for (int ks = 0; ks < 16; ks += 8) {
            uint32_t afh[4][4], afl[4][4], bfh[4][2], bfl[4][2];
            #pragma unroll
            for (int i = 0; i < 4; i++) {
                int m0 = wm * 64 + i * 16;
                afh[i][0] = As[0][ks + tig][m0 + gid];
                afh[i][1] = As[0][ks + tig][m0 + gid + 8];
                afh[i][2] = As[0][ks + tig + 4][m0 + gid];
                afh[i][3] = As[0][ks + tig + 4][m0 + gid + 8];
                afl[i][0] = As[1][ks + tig][m0 + gid];
                afl[i][1] = As[1][ks + tig][m0 + gid + 8];
                afl[i][2] = As[1][ks + tig + 4][m0 + gid];
                afl[i][3] = As[1][ks + tig + 4][m0 + gid + 8];
            }
            #pragma unroll
            for (int j = 0; j < 4; j++) {
                int n0 = wn * 32 + j * 8;
                bfh[j][0] = Bs[0][ks + tig][n0 + gid];
                bfh[j][1] = Bs[0][ks + tig + 4][n0 + gid];
                bfl[j][0] = Bs[1][ks + tig][n0 + gid];
                bfl[j][1] = Bs[1][ks + tig + 4][n0 + gid];
            }
            #pragma unroll
            for (int i = 0; i < 4; i++)
                #pragma unroll
                for (int j = 0; j < 4; j++)
                    mma3(acc[i][j], afh[i], afl[i], bfh[j], bfl[j]);
        }
        __syncthreads();
    }

    #pragma unroll
    for (int i = 0; i < 4; i++) {
        int row = by * 128 + wm * 64 + i * 16 + gid;
        #pragma unroll
        for (int j = 0; j < 4; j++) {
            int col = bx * 128 + wn * 32 + j * 8 + tig * 2;
            float b0 = bias ? bias[col] : 0.f;
            float b1 = bias ? bias[col + 1] : 0.f;
            *(float2*)(C + (size_t)row * N + col) =
                make_float2(acc[i][j][0] + b0, acc[i][j][1] + b1);
            *(float2*)(C + (size_t)(row + 8) * N + col) =
                make_float2(acc[i][j][2] + b0, acc[i][j][3] + b1);
        }
    }
}

// ---------------------------------------------------------------------------
extern "C" void kernel_launch(void* const* d_in, const int* in_sizes, int n_in,
                              void* d_out, int out_size)
{
    const float* x    = (const float*)d_in[0];
    const float* Wqkv = (const float*)d_in[1];
    const float* bqkv = (const float*)d_in[2];
    const float* Wout = (const float*)d_in[3];
    const float* bout = (const float*)d_in[4];
    float* out = (float*)d_out;

    float *qkv_ptr, *sc_ptr, *ctx_ptr;
    cudaGetSymbolAddress((void**)&qkv_ptr, g_qkv);
    cudaGetSymbolAddress((void**)&sc_ptr,  g_scores);
    cudaGetSymbolAddress((void**)&ctx_ptr, g_ctx);

    // 1) QKV projection (fp32, decision-critical, double-buffered)
    sgemm_bias_kernel<<<dim3(QKVN / 128, (BATCH * NSEQ) / 128), 256>>>(
        x, Wqkv, bqkv, qkv_ptr, BATCH * NSEQ, QKVN, DIM);

    // 2) Attention scores (fp32, double-buffered) + fused per-tile row stats
    scores_kernel<<<dim3(NSEQ / 128, NSEQ / 128, BATCH * HEADS), 256>>>(sc_ptr);

    // 3) Combine stats + select surviving attention entries (log-domain scan)
    select_kernel<<<(int)NROWS, 256>>>(sc_ptr);

    // 4) Sparse P@V (one warp per row; ~0.4 survivors/row)
    spv_kernel<<<(int)(NROWS * 32 / 256), 256>>>();

    // 5) Output projection (3xTF32 tensor path)
    sgemm_mma_bias<<<dim3(INNER / 128, (BATCH * NSEQ) / 128), 256>>>(
        ctx_ptr, Wout, bout, out, BATCH * NSEQ, INNER, INNER);
}